// round 8
// baseline (speedup 1.0000x reference)
#include <cuda_runtime.h>
#include <cuda_bf16.h>

#define T_IN   4096
#define T2     8192
#define C_CH   512
#define B_N    16
#define THREADS 128
#define TOUT    8
#define SEGS   4
// staged x: raw [start-8, start+1031] = 1040 floats = 260 float4,
// padded +1 float4 per 8 -> 293 float4 slots
#define SXN4_RAW 260
#define SXN4_PAD 293

// padded indexing: float4 idx -> idx + idx/8 ; float idx -> f + 4*(f/32)
#define PAD4(i)  ((i) + ((i) >> 3))
#define PADF(f)  ((f) + (((f) >> 5) << 2))

// kaiser_sinc_filter1d(0.25, 0.3, 12) — precomputed, symmetric (h[k]==h[11-k]).
#define H0 0.00202897f
#define H1 0.00938893f
#define H2 (-0.02554347f)
#define H3 (-0.05765742f)
#define H4 0.12857272f
#define H5 0.44321013f

// Up-sampling polyphase taps (2x gain folded in):
// even u=2s:   y = sum_m UE[m]*x[s+m-3],  UE[m] = 2*h[11-2m]
// odd  u=2s+1: y = sum_m UO[m]*x[s+m-2],  UO[m] = 2*h[10-2m]
__device__ constexpr float UE[6] = { 2.0f*H0, 2.0f*H2, 2.0f*H4, 2.0f*H5, 2.0f*H3, 2.0f*H1 };
__device__ constexpr float UO[6] = { 2.0f*H1, 2.0f*H3, 2.0f*H5, 2.0f*H4, 2.0f*H2, 2.0f*H0 };
// Down-sampling taps
__device__ constexpr float DD[12] = { H0, H1, H2, H3, H4, H5, H5, H4, H3, H2, H1, H0 };

__global__ __launch_bounds__(THREADS, 8)   // 64-reg budget, full-occ capable
void aa_act_kernel(const float* __restrict__ x,
                   const float* __restrict__ alpha,
                   const float* __restrict__ beta,
                   const float* __restrict__ uf,   // unused: taps are immediates
                   const float* __restrict__ df,   // unused
                   float* __restrict__ out)
{
    __shared__ __align__(16) float4 sx4[SXN4_PAD];
    float* sxf = reinterpret_cast<float*>(sx4);

    const int bx    = blockIdx.x;
    const int r     = bx >> 2;        // row = b*C + c
    const int seg   = bx & 3;
    const int start = seg << 10;
    const int c     = r & (C_CH - 1);
    const int tid   = threadIdx.x;
    const int base  = start - 8;      // raw x index of logical sx[0]

    const float* xrow = x + (size_t)r * T_IN;
    float* orow       = out + (size_t)r * T_IN;

    // ---- Vectorized staging into padded smem: logical sx[i] = x[clamp(base+i)] ----
    if (seg == 0) {
        // logical sx[0..7] = x[0] (left clamp); sx[8..1039] = x[0..1031]
        const float4* s4p = reinterpret_cast<const float4*>(xrow);
#pragma unroll
        for (int it = 0; it < 3; ++it) {
            int i = tid + it * THREADS;
            if (i < 258) sx4[PAD4(i + 2)] = __ldg(s4p + i);
        }
        if (tid < 8) sxf[PADF(tid)] = __ldg(xrow);
    } else if (seg == 3) {
        // sx[0..1031] = x[3064..4095]; sx[1032..1039] = x[4095] (right clamp)
        const float4* s4p = reinterpret_cast<const float4*>(xrow + 3064);
#pragma unroll
        for (int it = 0; it < 3; ++it) {
            int i = tid + it * THREADS;
            if (i < 258) sx4[PAD4(i)] = __ldg(s4p + i);
        }
        if (tid < 8) sxf[PADF(1032 + tid)] = __ldg(xrow + (T_IN - 1));
    } else {
        // fully interior: sx[0..1039] = x[start-8 .. start+1031]
        const float4* s4p = reinterpret_cast<const float4*>(xrow + (start - 8));
#pragma unroll
        for (int it = 0; it < 3; ++it) {
            int i = tid + it * THREADS;
            if (i < 260) sx4[PAD4(i)] = __ldg(s4p + i);
        }
    }

    const float ea    = __expf(__ldg(alpha + c));
    const float ieb   = 1.0f / (__expf(__ldg(beta + c)) + 1e-9f);
    const float ea2   = 2.0f * ea;     // cos(2*ea*y)
    const float ieb2  = 0.5f * ieb;    // snake: y + ieb2 - ieb2*cos(2*ea*y)
    const float nieb2 = -ieb2;

    __syncthreads();

    const int t0 = start + tid * TOUT;
    // fast iff y window [2t0-5, 2t0+20] needs no clamping
    const bool fast_ok = (t0 >= 3) && (t0 <= 4085);

    if (fast_ok) {
        // x window raw [t0-8, t0+15] -> rx[0..23]; logical float4 index 2*tid+i
        float rx[24];
#pragma unroll
        for (int i = 0; i < 6; i++) {
            const int li = 2 * tid + i;
            float4 v = sx4[PAD4(li)];
            rx[4 * i + 0] = v.x; rx[4 * i + 1] = v.y;
            rx[4 * i + 2] = v.z; rx[4 * i + 3] = v.w;
        }

        float acc[TOUT];
#pragma unroll
        for (int q = 0; q < TOUT; q++) acc[q] = ieb2;   // folded snake constant

        // y index u = 2*t0 - 5 + j, j=0..25; step i handles j=2i (u odd), j=2i+1 (u even)
#pragma unroll
        for (int i = 0; i < 13; ++i) {
            float yo = UO[0] * rx[i + 3];
            float ye = UE[0] * rx[i + 3];
#pragma unroll
            for (int m = 1; m < 6; ++m) {
                yo = fmaf(UO[m], rx[i + 3 + m], yo);
                ye = fmaf(UE[m], rx[i + 3 + m], ye);
            }
            // snake (3 ops): w = y - ieb2*cos(2*ea*y)   (+ieb2 folded into acc init)
            float co = __cosf(yo * ea2);
            float ce = __cosf(ye * ea2);
            yo = fmaf(nieb2, co, yo);
            ye = fmaf(nieb2, ce, ye);
            // scatter: y[j] feeds acc[q] with tap k = j - 2q in [0,12)
#pragma unroll
            for (int q = 0; q < TOUT; ++q) {
                const int k0 = 2 * i - 2 * q;       // yo (j = 2i)
                if (k0 >= 0 && k0 < 12) acc[q] = fmaf(DD[k0], yo, acc[q]);
                const int k1 = 2 * i + 1 - 2 * q;   // ye (j = 2i+1)
                if (k1 >= 0 && k1 < 12) acc[q] = fmaf(DD[k1], ye, acc[q]);
            }
        }

        *reinterpret_cast<float4*>(orow + t0)     = make_float4(acc[0], acc[1], acc[2], acc[3]);
        *reinterpret_cast<float4*>(orow + t0 + 4) = make_float4(acc[4], acc[5], acc[6], acc[7]);
    } else {
        // Edge path (t0==0 or t0==4088): y-index clamping, padded scalar smem reads.
        float acc[TOUT];
#pragma unroll
        for (int q = 0; q < TOUT; q++) acc[q] = ieb2;

#pragma unroll 1
        for (int j = 0; j < 26; ++j) {
            int u = 2 * t0 - 5 + j;
            u = u < 0 ? 0 : (u > T2 - 1 ? T2 - 1 : u);
            const int s   = u >> 1;
            const int idx = s - base;
            float yv;
            if (u & 1) {
                yv = UO[0] * sxf[PADF(idx - 2)];
#pragma unroll
                for (int m = 1; m < 6; ++m) yv = fmaf(UO[m], sxf[PADF(idx + m - 2)], yv);
            } else {
                yv = UE[0] * sxf[PADF(idx - 3)];
#pragma unroll
                for (int m = 1; m < 6; ++m) yv = fmaf(UE[m], sxf[PADF(idx + m - 3)], yv);
            }
            float cc = __cosf(yv * ea2);
            yv = fmaf(nieb2, cc, yv);
#pragma unroll
            for (int q = 0; q < TOUT; ++q) {
                const int k = j - 2 * q;
                if (k >= 0 && k < 12) acc[q] = fmaf(DD[k], yv, acc[q]);
            }
        }
#pragma unroll
        for (int q = 0; q < TOUT; q++) orow[t0 + q] = acc[q];
    }
}

extern "C" void kernel_launch(void* const* d_in, const int* in_sizes, int n_in,
                              void* d_out, int out_size) {
    const float* x     = (const float*)d_in[0];
    const float* alpha = (const float*)d_in[1];
    const float* beta  = (const float*)d_in[2];
    const float* uf    = (const float*)d_in[3];
    const float* df    = (const float*)d_in[4];
    float* out = (float*)d_out;

    dim3 grid(B_N * C_CH * SEGS);   // 32768 blocks
    aa_act_kernel<<<grid, THREADS>>>(x, alpha, beta, uf, df, out);
}